// round 1
// baseline (speedup 1.0000x reference)
#include <cuda_runtime.h>
#include <math.h>

#define BB 2
#define SS 1024
#define HIDN 4096
#define NH 32
#define NKV 8
#define HD 128
#define MTOK (BB*SS)           // 2048 tokens
#define KVW (NKV*HD)           // 1024

// ---------------- scratch (device globals; no allocation allowed) ----------------
__device__ float g_Q[(size_t)MTOK * HIDN];   // 33.5 MB
__device__ float g_K[(size_t)MTOK * KVW];    //  8.4 MB
__device__ float g_V[(size_t)MTOK * KVW];    //  8.4 MB
__device__ float g_C[(size_t)MTOK * HIDN];   // 33.5 MB (attention context)

// ============================================================================
// GEMM (NT): C[M,N] = A[M,K] @ B[N,K]^T.  A,B,C row-major.
// 128x128 tile, BK=16, 256 threads, 8x8 per-thread microtile with split halves
// (rows ty*4+i and 64+ty*4+i; cols tx*4+j and 64+tx*4+j) so all smem compute
// loads are conflict-free LDS.128.
// ============================================================================
__global__ __launch_bounds__(256) void gemm_nt(const float* __restrict__ A,
                                               const float* __restrict__ B,
                                               float* __restrict__ C,
                                               int M, int N, int K)
{
    __shared__ __align__(16) float As[16 * 132];
    __shared__ __align__(16) float Bs[16 * 132];

    const int tid = threadIdx.x;
    const int tx = tid & 15, ty = tid >> 4;
    const int brow = blockIdx.y * 128;
    const int bcol = blockIdx.x * 128;
    const float* Ab = A + (size_t)brow * K;
    const float* Bb = B + (size_t)bcol * K;

    float acc[8][8];
#pragma unroll
    for (int i = 0; i < 8; ++i)
#pragma unroll
        for (int j = 0; j < 8; ++j) acc[i][j] = 0.f;

    for (int k0 = 0; k0 < K; k0 += 16) {
#pragma unroll
        for (int i = 0; i < 2; ++i) {
            int id = tid + i * 256;
            int r = id >> 2;
            int c4 = (id & 3) * 4;
            float4 av = *(const float4*)(Ab + (size_t)r * K + k0 + c4);
            float4 bv = *(const float4*)(Bb + (size_t)r * K + k0 + c4);
            As[(c4 + 0) * 132 + r] = av.x;
            As[(c4 + 1) * 132 + r] = av.y;
            As[(c4 + 2) * 132 + r] = av.z;
            As[(c4 + 3) * 132 + r] = av.w;
            Bs[(c4 + 0) * 132 + r] = bv.x;
            Bs[(c4 + 1) * 132 + r] = bv.y;
            Bs[(c4 + 2) * 132 + r] = bv.z;
            Bs[(c4 + 3) * 132 + r] = bv.w;
        }
        __syncthreads();
#pragma unroll
        for (int k = 0; k < 16; ++k) {
            float4 a0 = *(const float4*)&As[k * 132 + ty * 4];
            float4 a1 = *(const float4*)&As[k * 132 + 64 + ty * 4];
            float4 b0 = *(const float4*)&Bs[k * 132 + tx * 4];
            float4 b1 = *(const float4*)&Bs[k * 132 + 64 + tx * 4];
            float ra[8] = {a0.x, a0.y, a0.z, a0.w, a1.x, a1.y, a1.z, a1.w};
            float rb[8] = {b0.x, b0.y, b0.z, b0.w, b1.x, b1.y, b1.z, b1.w};
#pragma unroll
            for (int i = 0; i < 8; ++i)
#pragma unroll
                for (int j = 0; j < 8; ++j)
                    acc[i][j] += ra[i] * rb[j];
        }
        __syncthreads();
    }

#pragma unroll
    for (int i = 0; i < 8; ++i) {
        int r = brow + ((i < 4) ? (ty * 4 + i) : (64 + ty * 4 + (i - 4)));
        float4 v0 = make_float4(acc[i][0], acc[i][1], acc[i][2], acc[i][3]);
        float4 v1 = make_float4(acc[i][4], acc[i][5], acc[i][6], acc[i][7]);
        *(float4*)(C + (size_t)r * N + bcol + tx * 4) = v0;
        *(float4*)(C + (size_t)r * N + bcol + 64 + tx * 4) = v1;
    }
}

// ============================================================================
// RoPE (in place). X: [MTOK, nheads*128]; pair i occupies dims (2i, 2i+1).
// Double precision angle computation for accuracy vs the fp32 reference.
// ============================================================================
__global__ void rope_kernel(float* __restrict__ X, int nheads)
{
    int idx = blockIdx.x * blockDim.x + threadIdx.x;
    int total = MTOK * nheads * 64;
    if (idx >= total) return;
    int i = idx & 63;
    int h = (idx >> 6) % nheads;
    int row = idx / (64 * nheads);
    int s = row & (SS - 1);

    double inv = exp(-(double)i * (log(10000.0) / 64.0));
    double fr = (double)s * inv;
    double sn, cs;
    sincos(fr, &sn, &cs);

    float* p = X + (size_t)row * (nheads * HD) + h * HD + 2 * i;
    float xe = p[0], xo = p[1];
    p[0] = (float)((double)xe * cs - (double)xo * sn);
    p[1] = (float)((double)xe * sn + (double)xo * cs);
}

// ============================================================================
// Causal flash attention, fp32.  Grid: (S/64, NH, BB). 256 threads (tx16 x ty16).
// Per thread: 4 score rows (ty*4+ii) x 4 score cols (tx*4+jj),
// O accumulator: 4 rows x 8 d-cols (tx*4+dd and 64+tx*4+dd).
// smem: Qt[128][68] Kt[128][68] (transposed, padded), Vs[64][132], Ps[64][68].
// ============================================================================
#define ATT_SMEM_FLOATS (2 * 128 * 68 + 64 * 132 + 64 * 68)
#define ATT_SMEM_BYTES (ATT_SMEM_FLOATS * 4)

__global__ __launch_bounds__(256) void attn_kernel(const float* __restrict__ Q,
                                                   const float* __restrict__ K,
                                                   const float* __restrict__ V,
                                                   float* __restrict__ O)
{
    extern __shared__ __align__(16) float sm[];
    float* Qt = sm;                          // [128][68]
    float* Kt = sm + 128 * 68;               // [128][68]
    float* Vs = sm + 2 * 128 * 68;           // [64][132]
    float* Ps = sm + 2 * 128 * 68 + 64 * 132;// [64][68]

    const int mb = blockIdx.x;
    const int h = blockIdx.y;
    const int b = blockIdx.z;
    const int kvh = h >> 2;   // N_REP = 4
    const int tid = threadIdx.x;
    const int tx = tid & 15, ty = tid >> 4;
    const float scale = 0.08838834764831845f;  // 1/sqrt(128)

    // Load Q tile (64 rows x 128 d), transposed into Qt[d][row]
    const float* Qb = Q + ((size_t)(b * SS + mb * 64)) * HIDN + h * HD;
#pragma unroll
    for (int t = 0; t < 8; ++t) {
        int id = tid + t * 256;
        int r = id >> 5;
        int c4 = (id & 31) * 4;
        float4 v = *(const float4*)(Qb + (size_t)r * HIDN + c4);
        Qt[(c4 + 0) * 68 + r] = v.x;
        Qt[(c4 + 1) * 68 + r] = v.y;
        Qt[(c4 + 2) * 68 + r] = v.z;
        Qt[(c4 + 3) * 68 + r] = v.w;
    }

    float m_r[4], l_r[4], o[4][8];
#pragma unroll
    for (int i = 0; i < 4; ++i) {
        m_r[i] = -INFINITY;
        l_r[i] = 0.f;
#pragma unroll
        for (int d = 0; d < 8; ++d) o[i][d] = 0.f;
    }

    for (int nb = 0; nb <= mb; ++nb) {
        const float* Kb = K + ((size_t)(b * SS + nb * 64)) * KVW + kvh * HD;
        const float* Vb = V + ((size_t)(b * SS + nb * 64)) * KVW + kvh * HD;
#pragma unroll
        for (int t = 0; t < 8; ++t) {
            int id = tid + t * 256;
            int r = id >> 5;
            int c4 = (id & 31) * 4;
            float4 kv = *(const float4*)(Kb + (size_t)r * KVW + c4);
            Kt[(c4 + 0) * 68 + r] = kv.x;
            Kt[(c4 + 1) * 68 + r] = kv.y;
            Kt[(c4 + 2) * 68 + r] = kv.z;
            Kt[(c4 + 3) * 68 + r] = kv.w;
            float4 vv = *(const float4*)(Vb + (size_t)r * KVW + c4);
            *(float4*)&Vs[r * 132 + c4] = vv;
        }
        __syncthreads();  // also covers Qt on first iteration

        // S = Q K^T (64x64), 4x4 per thread
        float s[4][4];
#pragma unroll
        for (int i = 0; i < 4; ++i)
#pragma unroll
            for (int j = 0; j < 4; ++j) s[i][j] = 0.f;

#pragma unroll 4
        for (int k = 0; k < 128; ++k) {
            float4 qa = *(const float4*)&Qt[k * 68 + ty * 4];
            float4 kb = *(const float4*)&Kt[k * 68 + tx * 4];
            float ra[4] = {qa.x, qa.y, qa.z, qa.w};
            float rb[4] = {kb.x, kb.y, kb.z, kb.w};
#pragma unroll
            for (int i = 0; i < 4; ++i)
#pragma unroll
                for (int j = 0; j < 4; ++j)
                    s[i][j] += ra[i] * rb[j];
        }

#pragma unroll
        for (int i = 0; i < 4; ++i)
#pragma unroll
            for (int j = 0; j < 4; ++j) s[i][j] *= scale;

        if (nb == mb) {
#pragma unroll
            for (int i = 0; i < 4; ++i)
#pragma unroll
                for (int j = 0; j < 4; ++j)
                    if (tx * 4 + j > ty * 4 + i) s[i][j] = -1e30f;
        }

        // online softmax per row
#pragma unroll
        for (int i = 0; i < 4; ++i) {
            float rm = fmaxf(fmaxf(s[i][0], s[i][1]), fmaxf(s[i][2], s[i][3]));
#pragma unroll
            for (int ofs = 1; ofs < 16; ofs <<= 1)
                rm = fmaxf(rm, __shfl_xor_sync(0xffffffffu, rm, ofs));
            float nm = fmaxf(m_r[i], rm);
            float corr = expf(m_r[i] - nm);
            float rs = 0.f;
#pragma unroll
            for (int j = 0; j < 4; ++j) {
                s[i][j] = expf(s[i][j] - nm);
                rs += s[i][j];
            }
#pragma unroll
            for (int ofs = 1; ofs < 16; ofs <<= 1)
                rs += __shfl_xor_sync(0xffffffffu, rs, ofs);
            l_r[i] = l_r[i] * corr + rs;
            m_r[i] = nm;
#pragma unroll
            for (int d = 0; d < 8; ++d) o[i][d] *= corr;
            *(float4*)&Ps[(ty * 4 + i) * 68 + tx * 4] =
                make_float4(s[i][0], s[i][1], s[i][2], s[i][3]);
        }
        __syncthreads();

        // O += P @ V
        for (int j = 0; j < 64; ++j) {
            float4 va = *(const float4*)&Vs[j * 132 + tx * 4];
            float4 vb = *(const float4*)&Vs[j * 132 + 64 + tx * 4];
#pragma unroll
            for (int i = 0; i < 4; ++i) {
                float p = Ps[(ty * 4 + i) * 68 + j];
                o[i][0] += p * va.x;
                o[i][1] += p * va.y;
                o[i][2] += p * va.z;
                o[i][3] += p * va.w;
                o[i][4] += p * vb.x;
                o[i][5] += p * vb.y;
                o[i][6] += p * vb.z;
                o[i][7] += p * vb.w;
            }
        }
        __syncthreads();  // before next tile overwrites Kt/Vs/Ps
    }

    // epilogue: normalize and store
    float* Ob = O + ((size_t)(b * SS + mb * 64)) * HIDN + h * HD;
#pragma unroll
    for (int i = 0; i < 4; ++i) {
        float inv = 1.f / l_r[i];
        int r = ty * 4 + i;
        float4 v0 = make_float4(o[i][0] * inv, o[i][1] * inv, o[i][2] * inv, o[i][3] * inv);
        float4 v1 = make_float4(o[i][4] * inv, o[i][5] * inv, o[i][6] * inv, o[i][7] * inv);
        *(float4*)(Ob + (size_t)r * HIDN + tx * 4) = v0;
        *(float4*)(Ob + (size_t)r * HIDN + 64 + tx * 4) = v1;
    }
}

// ============================================================================
// Launch
// ============================================================================
extern "C" void kernel_launch(void* const* d_in, const int* in_sizes, int n_in,
                              void* d_out, int out_size)
{
    (void)in_sizes; (void)n_in; (void)out_size;
    const float* hs = (const float*)d_in[0];
    const float* Wq = (const float*)d_in[1];
    const float* Wk = (const float*)d_in[2];
    const float* Wv = (const float*)d_in[3];
    const float* Wo = (const float*)d_in[4];
    float* out = (float*)d_out;

    float *qp, *kp, *vp, *cp;
    cudaGetSymbolAddress((void**)&qp, g_Q);
    cudaGetSymbolAddress((void**)&kp, g_K);
    cudaGetSymbolAddress((void**)&vp, g_V);
    cudaGetSymbolAddress((void**)&cp, g_C);

    cudaFuncSetAttribute(attn_kernel,
                         cudaFuncAttributeMaxDynamicSharedMemorySize,
                         ATT_SMEM_BYTES);

    dim3 blk(256);

    // Q/K/V projections
    gemm_nt<<<dim3(HIDN / 128, MTOK / 128), blk>>>(hs, Wq, qp, MTOK, HIDN, HIDN);
    gemm_nt<<<dim3(KVW / 128, MTOK / 128), blk>>>(hs, Wk, kp, MTOK, KVW, HIDN);
    gemm_nt<<<dim3(KVW / 128, MTOK / 128), blk>>>(hs, Wv, vp, MTOK, KVW, HIDN);

    // RoPE
    rope_kernel<<<(MTOK * NH * 64) / 256, 256>>>(qp, NH);
    rope_kernel<<<(MTOK * NKV * 64) / 256, 256>>>(kp, NKV);

    // causal attention
    attn_kernel<<<dim3(SS / 64, NH, BB), blk, ATT_SMEM_BYTES>>>(qp, kp, vp, cp);

    // output projection
    gemm_nt<<<dim3(HIDN / 128, MTOK / 128), blk>>>(cp, Wo, out, MTOK, HIDN, HIDN);
}

// round 4
// speedup vs baseline: 2.1459x; 2.1459x over previous
#include <cuda_runtime.h>
#include <cuda_bf16.h>
#include <math.h>
#include <stdint.h>

#define BB 2
#define SS 1024
#define HIDN 4096
#define NH 32
#define NKV 8
#define HD 128
#define MTOK (BB*SS)
#define KVW (NKV*HD)

typedef __nv_bfloat16 bf16;

// ---------------- scratch ----------------
__device__ float g_Q[(size_t)MTOK * HIDN];
__device__ float g_K[(size_t)MTOK * KVW];
__device__ float g_V[(size_t)MTOK * KVW];
__device__ float g_C[(size_t)MTOK * HIDN];
__device__ float g_rope[SS * 64 * 2];

__device__ bf16 g_hs_h[(size_t)MTOK * HIDN], g_hs_l[(size_t)MTOK * HIDN];
__device__ bf16 g_wq_h[(size_t)HIDN * HIDN], g_wq_l[(size_t)HIDN * HIDN];
__device__ bf16 g_wk_h[(size_t)KVW * HIDN],  g_wk_l[(size_t)KVW * HIDN];
__device__ bf16 g_wv_h[(size_t)KVW * HIDN],  g_wv_l[(size_t)KVW * HIDN];
__device__ bf16 g_wo_h[(size_t)HIDN * HIDN], g_wo_l[(size_t)HIDN * HIDN];
__device__ bf16 g_c_h[(size_t)MTOK * HIDN],  g_c_l[(size_t)MTOK * HIDN];

// ============================ helpers ====================================
__device__ __forceinline__ uint32_t smem_u32(const void* p) {
    uint32_t a;
    asm("{ .reg .u64 t; cvta.to.shared.u64 t, %1; cvt.u32.u64 %0, t; }" : "=r"(a) : "l"(p));
    return a;
}
__device__ __forceinline__ void cp16(uint32_t sdst, const void* gsrc) {
    asm volatile("cp.async.cg.shared.global [%0], [%1], 16;" :: "r"(sdst), "l"(gsrc));
}
__device__ __forceinline__ void cp_commit() {
    asm volatile("cp.async.commit_group;" ::: "memory");
}
template<int N> __device__ __forceinline__ void cp_wait() {
    asm volatile("cp.async.wait_group %0;" :: "n"(N) : "memory");
}
__device__ __forceinline__ void ldmx4(uint32_t* r, uint32_t addr) {
    asm volatile("ldmatrix.sync.aligned.m8n8.x4.shared.b16 {%0,%1,%2,%3}, [%4];"
                 : "=r"(r[0]), "=r"(r[1]), "=r"(r[2]), "=r"(r[3]) : "r"(addr));
}
__device__ __forceinline__ void ldmx2(uint32_t* r, uint32_t addr) {
    asm volatile("ldmatrix.sync.aligned.m8n8.x2.shared.b16 {%0,%1}, [%2];"
                 : "=r"(r[0]), "=r"(r[1]) : "r"(addr));
}
__device__ __forceinline__ void mma_bf16(float* c, const uint32_t* a, const uint32_t* b) {
    asm volatile(
        "mma.sync.aligned.m16n8k16.row.col.f32.bf16.bf16.f32 "
        "{%0,%1,%2,%3}, {%4,%5,%6,%7}, {%8,%9}, {%0,%1,%2,%3};"
        : "+f"(c[0]), "+f"(c[1]), "+f"(c[2]), "+f"(c[3])
        : "r"(a[0]), "r"(a[1]), "r"(a[2]), "r"(a[3]), "r"(b[0]), "r"(b[1]));
}

// ============================================================================
// Split-bf16 NT GEMM via mma.sync: C[M,N](fp32) = (Ah+Al)[M,K] @ (Bh+Bl)[N,K]^T
// (3 passes: AhBh + AhBl + AlBh). 128x128 CTA tile, 8 warps (64x32 each),
// BK=32, double-buffered cp.async. Smem rows padded to 80B (ldmatrix
// conflict-free).
// ============================================================================
#define GBK 32
#define ROWB 80                 // bytes per smem row (64 data + 16 pad)
#define ARR_B (128 * ROWB)      // 10240 bytes per array
#define BUF_B (4 * ARR_B)       // 40960 bytes per buffer
#define GSM_BYTES (2 * BUF_B)   // 81920

__global__ __launch_bounds__(256, 1) void gemm_hmma(const bf16* __restrict__ Ah,
                                                    const bf16* __restrict__ Al,
                                                    const bf16* __restrict__ Bh,
                                                    const bf16* __restrict__ Bl,
                                                    float* __restrict__ C,
                                                    int M, int N, int K)
{
    extern __shared__ __align__(128) char sm[];
    const uint32_t smb = smem_u32(sm);
    const int tid = threadIdx.x;
    const int warp = tid >> 5, lane = tid & 31;
    const int wm = warp >> 2, wn = warp & 3;          // 2 x 4 warp grid
    const int tn = blockIdx.x * 128;
    const int tm = blockIdx.y * 128;

    const char* gsrc[4];
    gsrc[0] = (const char*)(Ah + (size_t)tm * K);
    gsrc[1] = (const char*)(Al + (size_t)tm * K);
    gsrc[2] = (const char*)(Bh + (size_t)tn * K);
    gsrc[3] = (const char*)(Bl + (size_t)tn * K);
    const size_t rowb = (size_t)K * 2;

    float acc[4][4][4];
#pragma unroll
    for (int mt = 0; mt < 4; ++mt)
#pragma unroll
        for (int nt = 0; nt < 4; ++nt)
#pragma unroll
            for (int q = 0; q < 4; ++q) acc[mt][nt][q] = 0.f;

    const int r_ld = tid >> 2;          // 0..63? no: 256 threads, id>>2 below
    (void)r_ld;

    const int nk = K / GBK;

    // ---- prologue: load chunk 0 into buffer 0 ----
    {
        const size_t coff = 0;
#pragma unroll
        for (int a4 = 0; a4 < 4; ++a4) {
#pragma unroll
            for (int i = 0; i < 2; ++i) {
                int id = tid + i * 256;
                int r = id >> 2;
                int c8 = id & 3;
                cp16(smb + a4 * ARR_B + r * ROWB + c8 * 16,
                     gsrc[a4] + (size_t)r * rowb + coff + c8 * 16);
            }
        }
        cp_commit();
    }

    int buf = 0;
    for (int kc = 0; kc < nk; ++kc) {
        if (kc + 1 < nk) {
            const size_t coff = (size_t)(kc + 1) * 64;   // GBK bf16 = 64 bytes
            const uint32_t sb = smb + (buf ^ 1) * BUF_B;
#pragma unroll
            for (int a4 = 0; a4 < 4; ++a4) {
#pragma unroll
                for (int i = 0; i < 2; ++i) {
                    int id = tid + i * 256;
                    int r = id >> 2;
                    int c8 = id & 3;
                    cp16(sb + a4 * ARR_B + r * ROWB + c8 * 16,
                         gsrc[a4] + (size_t)r * rowb + coff + c8 * 16);
                }
            }
            cp_commit();
            cp_wait<1>();
        } else {
            cp_wait<0>();
        }
        __syncthreads();

        const uint32_t sAh = smb + buf * BUF_B + 0 * ARR_B;
        const uint32_t sAl = smb + buf * BUF_B + 1 * ARR_B;
        const uint32_t sBh = smb + buf * BUF_B + 2 * ARR_B;
        const uint32_t sBl = smb + buf * BUF_B + 3 * ARR_B;

#pragma unroll
        for (int ks = 0; ks < 2; ++ks) {
            uint32_t ah[4][4], al[4][4], bh[4][2], bl[4][2];
            const uint32_t acol = ks * 32 + (lane >> 4) * 16;
            const uint32_t bcol = ks * 32 + ((lane >> 3) & 1) * 16;
#pragma unroll
            for (int mt = 0; mt < 4; ++mt) {
                uint32_t roff = (uint32_t)(wm * 64 + mt * 16 + (lane & 15)) * ROWB + acol;
                ldmx4(ah[mt], sAh + roff);
                ldmx4(al[mt], sAl + roff);
            }
#pragma unroll
            for (int nt = 0; nt < 4; ++nt) {
                uint32_t roff = (uint32_t)(wn * 32 + nt * 8 + (lane & 7)) * ROWB + bcol;
                ldmx2(bh[nt], sBh + roff);
                ldmx2(bl[nt], sBl + roff);
            }
#pragma unroll
            for (int mt = 0; mt < 4; ++mt)
#pragma unroll
                for (int nt = 0; nt < 4; ++nt) {
                    mma_bf16(acc[mt][nt], ah[mt], bh[nt]);
                    mma_bf16(acc[mt][nt], ah[mt], bl[nt]);
                    mma_bf16(acc[mt][nt], al[mt], bh[nt]);
                }
        }
        __syncthreads();
        buf ^= 1;
    }

    // ---- epilogue ----
#pragma unroll
    for (int mt = 0; mt < 4; ++mt) {
        int row0 = tm + wm * 64 + mt * 16 + (lane >> 2);
#pragma unroll
        for (int nt = 0; nt < 4; ++nt) {
            int col = tn + wn * 32 + nt * 8 + (lane & 3) * 2;
            *(float2*)(C + (size_t)row0 * N + col) = make_float2(acc[mt][nt][0], acc[mt][nt][1]);
            *(float2*)(C + (size_t)(row0 + 8) * N + col) = make_float2(acc[mt][nt][2], acc[mt][nt][3]);
        }
    }
}

// ============================================================================
// fp32 -> bf16 hi/lo split
// ============================================================================
__global__ void cvt_split(const float* __restrict__ in, bf16* __restrict__ hi,
                          bf16* __restrict__ lo, int n4)
{
    int i = blockIdx.x * blockDim.x + threadIdx.x;
    if (i >= n4) return;
    float4 v = ((const float4*)in)[i];
    bf16 h[4], l[4];
    float x[4] = {v.x, v.y, v.z, v.w};
#pragma unroll
    for (int j = 0; j < 4; ++j) {
        h[j] = __float2bfloat16(x[j]);
        l[j] = __float2bfloat16(x[j] - __bfloat162float(h[j]));
    }
    *(uint2*)(hi + (size_t)i * 4) = *(uint2*)h;
    *(uint2*)(lo + (size_t)i * 4) = *(uint2*)l;
}

// ============================================================================
// RoPE: table + apply
// ============================================================================
__global__ void rope_table()
{
    int idx = blockIdx.x * blockDim.x + threadIdx.x;
    if (idx >= SS * 64) return;
    int s = idx >> 6, i = idx & 63;
    double inv = exp(-(double)i * (log(10000.0) / 64.0));
    double sn, cs;
    sincos((double)s * inv, &sn, &cs);
    g_rope[idx * 2 + 0] = (float)cs;
    g_rope[idx * 2 + 1] = (float)sn;
}

__global__ void rope_apply(float* __restrict__ X, int nheads)
{
    int idx = blockIdx.x * blockDim.x + threadIdx.x;
    int total = MTOK * nheads * 64;
    if (idx >= total) return;
    int i = idx & 63;
    int h = (idx >> 6) % nheads;
    int row = idx / (64 * nheads);
    int s = row & (SS - 1);
    float2 cs = *(const float2*)&g_rope[(s * 64 + i) * 2];
    float2* p = (float2*)(X + (size_t)row * (nheads * HD) + h * HD + 2 * i);
    float2 x = *p;
    float2 o;
    o.x = x.x * cs.x - x.y * cs.y;
    o.y = x.x * cs.y + x.y * cs.x;
    *p = o;
}

// ============================================================================
// Causal flash attention, fp32
// ============================================================================
#define ATT_SMEM_FLOATS (2 * 128 * 68 + 64 * 132 + 64 * 68)
#define ATT_SMEM_BYTES (ATT_SMEM_FLOATS * 4)

__global__ __launch_bounds__(256) void attn_kernel(const float* __restrict__ Q,
                                                   const float* __restrict__ K,
                                                   const float* __restrict__ V,
                                                   float* __restrict__ O)
{
    extern __shared__ __align__(16) float smf[];
    float* Qt = smf;
    float* Kt = smf + 128 * 68;
    float* Vs = smf + 2 * 128 * 68;
    float* Ps = smf + 2 * 128 * 68 + 64 * 132;

    const int mb = blockIdx.x;
    const int h = blockIdx.y;
    const int b = blockIdx.z;
    const int kvh = h >> 2;
    const int tid = threadIdx.x;
    const int tx = tid & 15, ty = tid >> 4;
    const float scale = 0.08838834764831845f;

    const float* Qb = Q + ((size_t)(b * SS + mb * 64)) * HIDN + h * HD;
#pragma unroll
    for (int t = 0; t < 8; ++t) {
        int id = tid + t * 256;
        int r = id >> 5;
        int c4 = (id & 31) * 4;
        float4 v = *(const float4*)(Qb + (size_t)r * HIDN + c4);
        Qt[(c4 + 0) * 68 + r] = v.x;
        Qt[(c4 + 1) * 68 + r] = v.y;
        Qt[(c4 + 2) * 68 + r] = v.z;
        Qt[(c4 + 3) * 68 + r] = v.w;
    }

    float m_r[4], l_r[4], o[4][8];
#pragma unroll
    for (int i = 0; i < 4; ++i) {
        m_r[i] = -INFINITY;
        l_r[i] = 0.f;
#pragma unroll
        for (int d = 0; d < 8; ++d) o[i][d] = 0.f;
    }

    for (int nb = 0; nb <= mb; ++nb) {
        const float* Kb = K + ((size_t)(b * SS + nb * 64)) * KVW + kvh * HD;
        const float* Vb = V + ((size_t)(b * SS + nb * 64)) * KVW + kvh * HD;
#pragma unroll
        for (int t = 0; t < 8; ++t) {
            int id = tid + t * 256;
            int r = id >> 5;
            int c4 = (id & 31) * 4;
            float4 kv = *(const float4*)(Kb + (size_t)r * KVW + c4);
            Kt[(c4 + 0) * 68 + r] = kv.x;
            Kt[(c4 + 1) * 68 + r] = kv.y;
            Kt[(c4 + 2) * 68 + r] = kv.z;
            Kt[(c4 + 3) * 68 + r] = kv.w;
            float4 vv = *(const float4*)(Vb + (size_t)r * KVW + c4);
            *(float4*)&Vs[r * 132 + c4] = vv;
        }
        __syncthreads();

        float s[4][4];
#pragma unroll
        for (int i = 0; i < 4; ++i)
#pragma unroll
            for (int j = 0; j < 4; ++j) s[i][j] = 0.f;

#pragma unroll 4
        for (int k = 0; k < 128; ++k) {
            float4 qa = *(const float4*)&Qt[k * 68 + ty * 4];
            float4 kb = *(const float4*)&Kt[k * 68 + tx * 4];
            float ra[4] = {qa.x, qa.y, qa.z, qa.w};
            float rb[4] = {kb.x, kb.y, kb.z, kb.w};
#pragma unroll
            for (int i = 0; i < 4; ++i)
#pragma unroll
                for (int j = 0; j < 4; ++j)
                    s[i][j] += ra[i] * rb[j];
        }

#pragma unroll
        for (int i = 0; i < 4; ++i)
#pragma unroll
            for (int j = 0; j < 4; ++j) s[i][j] *= scale;

        if (nb == mb) {
#pragma unroll
            for (int i = 0; i < 4; ++i)
#pragma unroll
                for (int j = 0; j < 4; ++j)
                    if (tx * 4 + j > ty * 4 + i) s[i][j] = -1e30f;
        }

#pragma unroll
        for (int i = 0; i < 4; ++i) {
            float rm = fmaxf(fmaxf(s[i][0], s[i][1]), fmaxf(s[i][2], s[i][3]));
#pragma unroll
            for (int ofs = 1; ofs < 16; ofs <<= 1)
                rm = fmaxf(rm, __shfl_xor_sync(0xffffffffu, rm, ofs));
            float nm = fmaxf(m_r[i], rm);
            float corr = expf(m_r[i] - nm);
            float rs = 0.f;
#pragma unroll
            for (int j = 0; j < 4; ++j) {
                s[i][j] = expf(s[i][j] - nm);
                rs += s[i][j];
            }
#pragma unroll
            for (int ofs = 1; ofs < 16; ofs <<= 1)
                rs += __shfl_xor_sync(0xffffffffu, rs, ofs);
            l_r[i] = l_r[i] * corr + rs;
            m_r[i] = nm;
#pragma unroll
            for (int d = 0; d < 8; ++d) o[i][d] *= corr;
            *(float4*)&Ps[(ty * 4 + i) * 68 + tx * 4] =
                make_float4(s[i][0], s[i][1], s[i][2], s[i][3]);
        }
        __syncthreads();

        for (int j = 0; j < 64; ++j) {
            float4 va = *(const float4*)&Vs[j * 132 + tx * 4];
            float4 vb = *(const float4*)&Vs[j * 132 + 64 + tx * 4];
#pragma unroll
            for (int i = 0; i < 4; ++i) {
                float p = Ps[(ty * 4 + i) * 68 + j];
                o[i][0] += p * va.x;
                o[i][1] += p * va.y;
                o[i][2] += p * va.z;
                o[i][3] += p * va.w;
                o[i][4] += p * vb.x;
                o[i][5] += p * vb.y;
                o[i][6] += p * vb.z;
                o[i][7] += p * vb.w;
            }
        }
        __syncthreads();
    }

    float* Ob = O + ((size_t)(b * SS + mb * 64)) * HIDN + h * HD;
#pragma unroll
    for (int i = 0; i < 4; ++i) {
        float inv = 1.f / l_r[i];
        int r = ty * 4 + i;
        float4 v0 = make_float4(o[i][0] * inv, o[i][1] * inv, o[i][2] * inv, o[i][3] * inv);
        float4 v1 = make_float4(o[i][4] * inv, o[i][5] * inv, o[i][6] * inv, o[i][7] * inv);
        *(float4*)(Ob + (size_t)r * HIDN + tx * 4) = v0;
        *(float4*)(Ob + (size_t)r * HIDN + 64 + tx * 4) = v1;
    }
}

// ============================================================================
// Launch
// ============================================================================
extern "C" void kernel_launch(void* const* d_in, const int* in_sizes, int n_in,
                              void* d_out, int out_size)
{
    (void)in_sizes; (void)n_in; (void)out_size;
    const float* hs = (const float*)d_in[0];
    const float* Wq = (const float*)d_in[1];
    const float* Wk = (const float*)d_in[2];
    const float* Wv = (const float*)d_in[3];
    const float* Wo = (const float*)d_in[4];
    float* out = (float*)d_out;

    float *qp, *kp, *vp, *cp;
    cudaGetSymbolAddress((void**)&qp, g_Q);
    cudaGetSymbolAddress((void**)&kp, g_K);
    cudaGetSymbolAddress((void**)&vp, g_V);
    cudaGetSymbolAddress((void**)&cp, g_C);
    bf16 *hsh, *hsl, *wqh, *wql, *wkh, *wkl, *wvh, *wvl, *woh, *wol, *ch, *cl;
    cudaGetSymbolAddress((void**)&hsh, g_hs_h); cudaGetSymbolAddress((void**)&hsl, g_hs_l);
    cudaGetSymbolAddress((void**)&wqh, g_wq_h); cudaGetSymbolAddress((void**)&wql, g_wq_l);
    cudaGetSymbolAddress((void**)&wkh, g_wk_h); cudaGetSymbolAddress((void**)&wkl, g_wk_l);
    cudaGetSymbolAddress((void**)&wvh, g_wv_h); cudaGetSymbolAddress((void**)&wvl, g_wv_l);
    cudaGetSymbolAddress((void**)&woh, g_wo_h); cudaGetSymbolAddress((void**)&wol, g_wo_l);
    cudaGetSymbolAddress((void**)&ch, g_c_h);   cudaGetSymbolAddress((void**)&cl, g_c_l);

    cudaFuncSetAttribute(attn_kernel, cudaFuncAttributeMaxDynamicSharedMemorySize, ATT_SMEM_BYTES);
    cudaFuncSetAttribute(gemm_hmma, cudaFuncAttributeMaxDynamicSharedMemorySize, GSM_BYTES);

    rope_table<<<(SS * 64 + 255) / 256, 256>>>();

    {
        int n;
        n = MTOK * HIDN / 4; cvt_split<<<(n + 255) / 256, 256>>>(hs, hsh, hsl, n);
        n = HIDN * HIDN / 4; cvt_split<<<(n + 255) / 256, 256>>>(Wq, wqh, wql, n);
        n = KVW * HIDN / 4;  cvt_split<<<(n + 255) / 256, 256>>>(Wk, wkh, wkl, n);
        n = KVW * HIDN / 4;  cvt_split<<<(n + 255) / 256, 256>>>(Wv, wvh, wvl, n);
        n = HIDN * HIDN / 4; cvt_split<<<(n + 255) / 256, 256>>>(Wo, woh, wol, n);
    }

    gemm_hmma<<<dim3(HIDN / 128, MTOK / 128), 256, GSM_BYTES>>>(hsh, hsl, wqh, wql, qp, MTOK, HIDN, HIDN);
    gemm_hmma<<<dim3(KVW / 128, MTOK / 128), 256, GSM_BYTES>>>(hsh, hsl, wkh, wkl, kp, MTOK, KVW, HIDN);
    gemm_hmma<<<dim3(KVW / 128, MTOK / 128), 256, GSM_BYTES>>>(hsh, hsl, wvh, wvl, vp, MTOK, KVW, HIDN);

    rope_apply<<<(MTOK * NH * 64 + 255) / 256, 256>>>(qp, NH);
    rope_apply<<<(MTOK * NKV * 64 + 255) / 256, 256>>>(kp, NKV);

    attn_kernel<<<dim3(SS / 64, NH, BB), 256, ATT_SMEM_BYTES>>>(qp, kp, vp, cp);

    {
        int n = MTOK * HIDN / 4;
        cvt_split<<<(n + 255) / 256, 256>>>(cp, ch, cl, n);
    }
    gemm_hmma<<<dim3(HIDN / 128, MTOK / 128), 256, GSM_BYTES>>>(ch, cl, woh, wol, out, MTOK, HIDN, HIDN);
}

// round 5
// speedup vs baseline: 2.7798x; 1.2954x over previous
#include <cuda_runtime.h>
#include <cuda_bf16.h>
#include <math.h>
#include <stdint.h>

#define BB 2
#define SS 1024
#define HIDN 4096
#define NH 32
#define NKV 8
#define HD 128
#define MTOK (BB*SS)
#define KVW (NKV*HD)

typedef __nv_bfloat16 bf16;

// ---------------- scratch ----------------
__device__ float g_Q[(size_t)MTOK * HIDN];
__device__ float g_K[(size_t)MTOK * KVW];
__device__ float g_V[(size_t)MTOK * KVW];
__device__ float g_C[(size_t)MTOK * HIDN];
__device__ float g_rope[SS * 64 * 2];

__device__ bf16 g_hs_h[(size_t)MTOK * HIDN], g_hs_l[(size_t)MTOK * HIDN];
__device__ bf16 g_wq_h[(size_t)HIDN * HIDN], g_wq_l[(size_t)HIDN * HIDN];
__device__ bf16 g_wk_h[(size_t)KVW * HIDN],  g_wk_l[(size_t)KVW * HIDN];
__device__ bf16 g_wv_h[(size_t)KVW * HIDN],  g_wv_l[(size_t)KVW * HIDN];
__device__ bf16 g_wo_h[(size_t)HIDN * HIDN], g_wo_l[(size_t)HIDN * HIDN];
__device__ bf16 g_c_h[(size_t)MTOK * HIDN],  g_c_l[(size_t)MTOK * HIDN];

// attention operands (bf16 hi/lo)
__device__ bf16 g_qh[(size_t)MTOK * HIDN], g_ql[(size_t)MTOK * HIDN];
__device__ bf16 g_kh[(size_t)MTOK * KVW],  g_kl[(size_t)MTOK * KVW];
__device__ bf16 g_vh[(size_t)MTOK * KVW],  g_vl[(size_t)MTOK * KVW];

// ============================ helpers ====================================
__device__ __forceinline__ uint32_t smem_u32(const void* p) {
    uint32_t a;
    asm("{ .reg .u64 t; cvta.to.shared.u64 t, %1; cvt.u32.u64 %0, t; }" : "=r"(a) : "l"(p));
    return a;
}
__device__ __forceinline__ void cp16(uint32_t sdst, const void* gsrc) {
    asm volatile("cp.async.cg.shared.global [%0], [%1], 16;" :: "r"(sdst), "l"(gsrc));
}
__device__ __forceinline__ void cp_commit() {
    asm volatile("cp.async.commit_group;" ::: "memory");
}
template<int N> __device__ __forceinline__ void cp_wait() {
    asm volatile("cp.async.wait_group %0;" :: "n"(N) : "memory");
}
__device__ __forceinline__ void ldmx4(uint32_t* r, uint32_t addr) {
    asm volatile("ldmatrix.sync.aligned.m8n8.x4.shared.b16 {%0,%1,%2,%3}, [%4];"
                 : "=r"(r[0]), "=r"(r[1]), "=r"(r[2]), "=r"(r[3]) : "r"(addr));
}
__device__ __forceinline__ void ldmx2(uint32_t* r, uint32_t addr) {
    asm volatile("ldmatrix.sync.aligned.m8n8.x2.shared.b16 {%0,%1}, [%2];"
                 : "=r"(r[0]), "=r"(r[1]) : "r"(addr));
}
__device__ __forceinline__ void ldmx2t(uint32_t* r, uint32_t addr) {
    asm volatile("ldmatrix.sync.aligned.m8n8.x2.trans.shared.b16 {%0,%1}, [%2];"
                 : "=r"(r[0]), "=r"(r[1]) : "r"(addr));
}
__device__ __forceinline__ void mma_bf16(float* c, const uint32_t* a, const uint32_t* b) {
    asm volatile(
        "mma.sync.aligned.m16n8k16.row.col.f32.bf16.bf16.f32 "
        "{%0,%1,%2,%3}, {%4,%5,%6,%7}, {%8,%9}, {%0,%1,%2,%3};"
        : "+f"(c[0]), "+f"(c[1]), "+f"(c[2]), "+f"(c[3])
        : "r"(a[0]), "r"(a[1]), "r"(a[2]), "r"(a[3]), "r"(b[0]), "r"(b[1]));
}
__device__ __forceinline__ uint16_t bfbits(bf16 h) { return *(uint16_t*)&h; }

// ============================================================================
// Split-bf16 NT GEMM via mma.sync (unchanged from round 4)
// ============================================================================
#define GBK 32
#define ROWB 80
#define ARR_B (128 * ROWB)
#define BUF_B (4 * ARR_B)
#define GSM_BYTES (2 * BUF_B)

__global__ __launch_bounds__(256, 1) void gemm_hmma(const bf16* __restrict__ Ah,
                                                    const bf16* __restrict__ Al,
                                                    const bf16* __restrict__ Bh,
                                                    const bf16* __restrict__ Bl,
                                                    float* __restrict__ C,
                                                    int M, int N, int K)
{
    extern __shared__ __align__(128) char sm[];
    const uint32_t smb = smem_u32(sm);
    const int tid = threadIdx.x;
    const int warp = tid >> 5, lane = tid & 31;
    const int wm = warp >> 2, wn = warp & 3;
    const int tn = blockIdx.x * 128;
    const int tm = blockIdx.y * 128;

    const char* gsrc[4];
    gsrc[0] = (const char*)(Ah + (size_t)tm * K);
    gsrc[1] = (const char*)(Al + (size_t)tm * K);
    gsrc[2] = (const char*)(Bh + (size_t)tn * K);
    gsrc[3] = (const char*)(Bl + (size_t)tn * K);
    const size_t rowb = (size_t)K * 2;

    float acc[4][4][4];
#pragma unroll
    for (int mt = 0; mt < 4; ++mt)
#pragma unroll
        for (int nt = 0; nt < 4; ++nt)
#pragma unroll
            for (int q = 0; q < 4; ++q) acc[mt][nt][q] = 0.f;

    const int nk = K / GBK;

    {
#pragma unroll
        for (int a4 = 0; a4 < 4; ++a4) {
#pragma unroll
            for (int i = 0; i < 2; ++i) {
                int id = tid + i * 256;
                int r = id >> 2;
                int c8 = id & 3;
                cp16(smb + a4 * ARR_B + r * ROWB + c8 * 16,
                     gsrc[a4] + (size_t)r * rowb + c8 * 16);
            }
        }
        cp_commit();
    }

    int buf = 0;
    for (int kc = 0; kc < nk; ++kc) {
        if (kc + 1 < nk) {
            const size_t coff = (size_t)(kc + 1) * 64;
            const uint32_t sb = smb + (buf ^ 1) * BUF_B;
#pragma unroll
            for (int a4 = 0; a4 < 4; ++a4) {
#pragma unroll
                for (int i = 0; i < 2; ++i) {
                    int id = tid + i * 256;
                    int r = id >> 2;
                    int c8 = id & 3;
                    cp16(sb + a4 * ARR_B + r * ROWB + c8 * 16,
                         gsrc[a4] + (size_t)r * rowb + coff + c8 * 16);
                }
            }
            cp_commit();
            cp_wait<1>();
        } else {
            cp_wait<0>();
        }
        __syncthreads();

        const uint32_t sAh = smb + buf * BUF_B + 0 * ARR_B;
        const uint32_t sAl = smb + buf * BUF_B + 1 * ARR_B;
        const uint32_t sBh = smb + buf * BUF_B + 2 * ARR_B;
        const uint32_t sBl = smb + buf * BUF_B + 3 * ARR_B;

#pragma unroll
        for (int ks = 0; ks < 2; ++ks) {
            uint32_t ah[4][4], al[4][4], bh[4][2], bl[4][2];
            const uint32_t acol = ks * 32 + (lane >> 4) * 16;
            const uint32_t bcol = ks * 32 + ((lane >> 3) & 1) * 16;
#pragma unroll
            for (int mt = 0; mt < 4; ++mt) {
                uint32_t roff = (uint32_t)(wm * 64 + mt * 16 + (lane & 15)) * ROWB + acol;
                ldmx4(ah[mt], sAh + roff);
                ldmx4(al[mt], sAl + roff);
            }
#pragma unroll
            for (int nt = 0; nt < 4; ++nt) {
                uint32_t roff = (uint32_t)(wn * 32 + nt * 8 + (lane & 7)) * ROWB + bcol;
                ldmx2(bh[nt], sBh + roff);
                ldmx2(bl[nt], sBl + roff);
            }
#pragma unroll
            for (int mt = 0; mt < 4; ++mt)
#pragma unroll
                for (int nt = 0; nt < 4; ++nt) {
                    mma_bf16(acc[mt][nt], ah[mt], bh[nt]);
                    mma_bf16(acc[mt][nt], ah[mt], bl[nt]);
                    mma_bf16(acc[mt][nt], al[mt], bh[nt]);
                }
        }
        __syncthreads();
        buf ^= 1;
    }

#pragma unroll
    for (int mt = 0; mt < 4; ++mt) {
        int row0 = tm + wm * 64 + mt * 16 + (lane >> 2);
#pragma unroll
        for (int nt = 0; nt < 4; ++nt) {
            int col = tn + wn * 32 + nt * 8 + (lane & 3) * 2;
            *(float2*)(C + (size_t)row0 * N + col) = make_float2(acc[mt][nt][0], acc[mt][nt][1]);
            *(float2*)(C + (size_t)(row0 + 8) * N + col) = make_float2(acc[mt][nt][2], acc[mt][nt][3]);
        }
    }
}

// ============================================================================
// fp32 -> bf16 hi/lo split (optional scale folded in)
// ============================================================================
__global__ void cvt_split(const float* __restrict__ in, bf16* __restrict__ hi,
                          bf16* __restrict__ lo, int n4)
{
    int i = blockIdx.x * blockDim.x + threadIdx.x;
    if (i >= n4) return;
    float4 v = ((const float4*)in)[i];
    bf16 h[4], l[4];
    float x[4] = {v.x, v.y, v.z, v.w};
#pragma unroll
    for (int j = 0; j < 4; ++j) {
        h[j] = __float2bfloat16(x[j]);
        l[j] = __float2bfloat16(x[j] - __bfloat162float(h[j]));
    }
    *(uint2*)(hi + (size_t)i * 4) = *(uint2*)h;
    *(uint2*)(lo + (size_t)i * 4) = *(uint2*)l;
}

__global__ void cvt_split_s(const float* __restrict__ in, bf16* __restrict__ hi,
                            bf16* __restrict__ lo, int n4, float scale)
{
    int i = blockIdx.x * blockDim.x + threadIdx.x;
    if (i >= n4) return;
    float4 v = ((const float4*)in)[i];
    bf16 h[4], l[4];
    float x[4] = {v.x * scale, v.y * scale, v.z * scale, v.w * scale};
#pragma unroll
    for (int j = 0; j < 4; ++j) {
        h[j] = __float2bfloat16(x[j]);
        l[j] = __float2bfloat16(x[j] - __bfloat162float(h[j]));
    }
    *(uint2*)(hi + (size_t)i * 4) = *(uint2*)h;
    *(uint2*)(lo + (size_t)i * 4) = *(uint2*)l;
}

// ============================================================================
// RoPE
// ============================================================================
__global__ void rope_table()
{
    int idx = blockIdx.x * blockDim.x + threadIdx.x;
    if (idx >= SS * 64) return;
    int s = idx >> 6, i = idx & 63;
    double inv = exp(-(double)i * (log(10000.0) / 64.0));
    double sn, cs;
    sincos((double)s * inv, &sn, &cs);
    g_rope[idx * 2 + 0] = (float)cs;
    g_rope[idx * 2 + 1] = (float)sn;
}

__global__ void rope_apply(float* __restrict__ X, int nheads)
{
    int idx = blockIdx.x * blockDim.x + threadIdx.x;
    int total = MTOK * nheads * 64;
    if (idx >= total) return;
    int i = idx & 63;
    int h = (idx >> 6) % nheads;
    int row = idx / (64 * nheads);
    int s = row & (SS - 1);
    float2 cs = *(const float2*)&g_rope[(s * 64 + i) * 2];
    float2* p = (float2*)(X + (size_t)row * (nheads * HD) + h * HD + 2 * i);
    float2 x = *p;
    float2 o;
    o.x = x.x * cs.x - x.y * cs.y;
    o.y = x.x * cs.y + x.y * cs.x;
    *p = o;
}

// ============================================================================
// HMMA flash attention (split bf16, 3-pass QK and PV).
// 64 Q rows x 64 KV tile x 128 d. 128 threads, warp w owns rows w*16..+15.
// Smem: 6 arrays [64 rows][256B] XOR-swizzled (Qh,Ql,Kh,Kl,Vh,Vl) = 96KB.
// ============================================================================
#define ASW(row, colu) ((uint32_t)(row) * 256 + ((((uint32_t)(colu)) ^ ((row) & 7)) << 4))
#define AT_Q_H 0
#define AT_Q_L 16384
#define AT_K_H 32768
#define AT_K_L 49152
#define AT_V_H 65536
#define AT_V_L 81920
#define AT_SMEM 98304

__global__ __launch_bounds__(128) void attn_hmma(const bf16* __restrict__ Qh,
                                                 const bf16* __restrict__ Ql,
                                                 const bf16* __restrict__ Kh,
                                                 const bf16* __restrict__ Kl,
                                                 const bf16* __restrict__ Vh,
                                                 const bf16* __restrict__ Vl,
                                                 float* __restrict__ O)
{
    extern __shared__ __align__(128) char sm[];
    const uint32_t smb = smem_u32(sm);
    const int mb = blockIdx.x;
    const int h = blockIdx.y;
    const int b = blockIdx.z;
    const int kvh = h >> 2;
    const int tid = threadIdx.x;
    const int warp = tid >> 5, lane = tid & 31;

    // ---- load Q tile (64 rows x 128 d, hi+lo) ----
    {
        const char* gqh = (const char*)(Qh + ((size_t)(b * SS + mb * 64)) * HIDN + h * HD);
        const char* gql = (const char*)(Ql + ((size_t)(b * SS + mb * 64)) * HIDN + h * HD);
#pragma unroll
        for (int t = 0; t < 8; ++t) {
            int id = tid + t * 128;
            int r = id >> 4;
            int cu = id & 15;
            cp16(smb + AT_Q_H + ASW(r, cu), gqh + (size_t)r * (HIDN * 2) + cu * 16);
            cp16(smb + AT_Q_L + ASW(r, cu), gql + (size_t)r * (HIDN * 2) + cu * 16);
        }
        cp_commit();
    }

    float o[16][4];
#pragma unroll
    for (int nt = 0; nt < 16; ++nt)
#pragma unroll
        for (int q = 0; q < 4; ++q) o[nt][q] = 0.f;
    float m_a = -INFINITY, m_b = -INFINITY, l_a = 0.f, l_b = 0.f;

    const int rowA = warp * 16 + (lane >> 2);       // local q row for c0,c1
    const int grow_a = mb * 64 + rowA;
    const int grow_b = grow_a + 8;

    for (int nb = 0; nb <= mb; ++nb) {
        // ---- load K,V tile ----
        {
            const char* gkh = (const char*)(Kh + ((size_t)(b * SS + nb * 64)) * KVW + kvh * HD);
            const char* gkl = (const char*)(Kl + ((size_t)(b * SS + nb * 64)) * KVW + kvh * HD);
            const char* gvh = (const char*)(Vh + ((size_t)(b * SS + nb * 64)) * KVW + kvh * HD);
            const char* gvl = (const char*)(Vl + ((size_t)(b * SS + nb * 64)) * KVW + kvh * HD);
#pragma unroll
            for (int t = 0; t < 8; ++t) {
                int id = tid + t * 128;
                int r = id >> 4;
                int cu = id & 15;
                size_t go = (size_t)r * (KVW * 2) + cu * 16;
                uint32_t so = ASW(r, cu);
                cp16(smb + AT_K_H + so, gkh + go);
                cp16(smb + AT_K_L + so, gkl + go);
                cp16(smb + AT_V_H + so, gvh + go);
                cp16(smb + AT_V_L + so, gvl + go);
            }
            cp_commit();
            cp_wait<0>();
        }
        __syncthreads();

        // ---- S = Q K^T (16x64 per warp), 3-pass split ----
        float s[8][4];
#pragma unroll
        for (int j = 0; j < 8; ++j)
#pragma unroll
            for (int q = 0; q < 4; ++q) s[j][q] = 0.f;

#pragma unroll
        for (int ks = 0; ks < 8; ++ks) {
            uint32_t ah[4], al[4];
            {
                int r = warp * 16 + (lane & 15);
                int cu = ks * 2 + (lane >> 4);
                ldmx4(ah, smb + AT_Q_H + ASW(r, cu));
                ldmx4(al, smb + AT_Q_L + ASW(r, cu));
            }
#pragma unroll
            for (int j = 0; j < 8; ++j) {
                uint32_t bh[2], bl[2];
                int r = j * 8 + (lane & 7);
                int cu = ks * 2 + ((lane >> 3) & 1);
                ldmx2(bh, smb + AT_K_H + ASW(r, cu));
                ldmx2(bl, smb + AT_K_L + ASW(r, cu));
                mma_bf16(s[j], ah, bh);
                mma_bf16(s[j], ah, bl);
                mma_bf16(s[j], al, bh);
            }
        }

        // ---- causal mask (diagonal tile only) ----
        if (nb == mb) {
#pragma unroll
            for (int j = 0; j < 8; ++j) {
                int col = nb * 64 + j * 8 + (lane & 3) * 2;
                if (col > grow_a)     s[j][0] = -1e30f;
                if (col + 1 > grow_a) s[j][1] = -1e30f;
                if (col > grow_b)     s[j][2] = -1e30f;
                if (col + 1 > grow_b) s[j][3] = -1e30f;
            }
        }

        // ---- online softmax (rows rowA and rowA+8) ----
        float mx_a = -INFINITY, mx_b = -INFINITY;
#pragma unroll
        for (int j = 0; j < 8; ++j) {
            mx_a = fmaxf(mx_a, fmaxf(s[j][0], s[j][1]));
            mx_b = fmaxf(mx_b, fmaxf(s[j][2], s[j][3]));
        }
        mx_a = fmaxf(mx_a, __shfl_xor_sync(0xffffffffu, mx_a, 1));
        mx_a = fmaxf(mx_a, __shfl_xor_sync(0xffffffffu, mx_a, 2));
        mx_b = fmaxf(mx_b, __shfl_xor_sync(0xffffffffu, mx_b, 1));
        mx_b = fmaxf(mx_b, __shfl_xor_sync(0xffffffffu, mx_b, 2));

        float nm_a = fmaxf(m_a, mx_a);
        float nm_b = fmaxf(m_b, mx_b);
        float corr_a = __expf(m_a - nm_a);
        float corr_b = __expf(m_b - nm_b);
        m_a = nm_a; m_b = nm_b;

        float sum_a = 0.f, sum_b = 0.f;
#pragma unroll
        for (int j = 0; j < 8; ++j) {
            s[j][0] = __expf(s[j][0] - nm_a);
            s[j][1] = __expf(s[j][1] - nm_a);
            s[j][2] = __expf(s[j][2] - nm_b);
            s[j][3] = __expf(s[j][3] - nm_b);
            sum_a += s[j][0] + s[j][1];
            sum_b += s[j][2] + s[j][3];
        }
        sum_a += __shfl_xor_sync(0xffffffffu, sum_a, 1);
        sum_a += __shfl_xor_sync(0xffffffffu, sum_a, 2);
        sum_b += __shfl_xor_sync(0xffffffffu, sum_b, 1);
        sum_b += __shfl_xor_sync(0xffffffffu, sum_b, 2);
        l_a = l_a * corr_a + sum_a;
        l_b = l_b * corr_b + sum_b;

#pragma unroll
        for (int nt = 0; nt < 16; ++nt) {
            o[nt][0] *= corr_a; o[nt][1] *= corr_a;
            o[nt][2] *= corr_b; o[nt][3] *= corr_b;
        }

        // ---- build P fragments (hi/lo) ----
        uint32_t ph[4][4], pl[4][4];
#pragma unroll
        for (int ks = 0; ks < 4; ++ks) {
            const float* t0 = s[2 * ks];
            const float* t1 = s[2 * ks + 1];
            float v0[8] = {t0[0], t0[1], t0[2], t0[3], t1[0], t1[1], t1[2], t1[3]};
            uint16_t hb[8]; float rs[8];
#pragma unroll
            for (int e = 0; e < 8; ++e) {
                bf16 hh = __float2bfloat16(v0[e]);
                hb[e] = bfbits(hh);
                rs[e] = v0[e] - __bfloat162float(hh);
            }
            ph[ks][0] = ((uint32_t)hb[1] << 16) | hb[0];
            ph[ks][1] = ((uint32_t)hb[3] << 16) | hb[2];
            ph[ks][2] = ((uint32_t)hb[5] << 16) | hb[4];
            ph[ks][3] = ((uint32_t)hb[7] << 16) | hb[6];
            uint16_t lb[8];
#pragma unroll
            for (int e = 0; e < 8; ++e) lb[e] = bfbits(__float2bfloat16(rs[e]));
            pl[ks][0] = ((uint32_t)lb[1] << 16) | lb[0];
            pl[ks][1] = ((uint32_t)lb[3] << 16) | lb[2];
            pl[ks][2] = ((uint32_t)lb[5] << 16) | lb[4];
            pl[ks][3] = ((uint32_t)lb[7] << 16) | lb[6];
        }

        // ---- O += P @ V (V via ldmatrix.trans), 3-pass ----
#pragma unroll
        for (int nt = 0; nt < 16; ++nt) {
#pragma unroll
            for (int ks = 0; ks < 4; ++ks) {
                uint32_t bh[2], bl[2];
                int r = ks * 16 + (lane & 15);
                ldmx2t(bh, smb + AT_V_H + ASW(r, nt));
                ldmx2t(bl, smb + AT_V_L + ASW(r, nt));
                mma_bf16(o[nt], ph[ks], bh);
                mma_bf16(o[nt], ph[ks], bl);
                mma_bf16(o[nt], pl[ks], bh);
            }
        }
        __syncthreads();
    }

    // ---- epilogue ----
    const float inv_a = 1.f / l_a;
    const float inv_b = 1.f / l_b;
    float* Oa = O + ((size_t)(b * SS + mb * 64 + rowA)) * HIDN + h * HD;
    float* Ob = Oa + (size_t)8 * HIDN;
#pragma unroll
    for (int nt = 0; nt < 16; ++nt) {
        int col = nt * 8 + (lane & 3) * 2;
        *(float2*)(Oa + col) = make_float2(o[nt][0] * inv_a, o[nt][1] * inv_a);
        *(float2*)(Ob + col) = make_float2(o[nt][2] * inv_b, o[nt][3] * inv_b);
    }
}

// ============================================================================
// Launch
// ============================================================================
extern "C" void kernel_launch(void* const* d_in, const int* in_sizes, int n_in,
                              void* d_out, int out_size)
{
    (void)in_sizes; (void)n_in; (void)out_size;
    const float* hs = (const float*)d_in[0];
    const float* Wq = (const float*)d_in[1];
    const float* Wk = (const float*)d_in[2];
    const float* Wv = (const float*)d_in[3];
    const float* Wo = (const float*)d_in[4];
    float* out = (float*)d_out;

    float *qp, *kp, *vp, *cp;
    cudaGetSymbolAddress((void**)&qp, g_Q);
    cudaGetSymbolAddress((void**)&kp, g_K);
    cudaGetSymbolAddress((void**)&vp, g_V);
    cudaGetSymbolAddress((void**)&cp, g_C);
    bf16 *hsh, *hsl, *wqh, *wql, *wkh, *wkl, *wvh, *wvl, *woh, *wol, *ch, *cl;
    bf16 *qh, *ql, *kh, *kl, *vh, *vl;
    cudaGetSymbolAddress((void**)&hsh, g_hs_h); cudaGetSymbolAddress((void**)&hsl, g_hs_l);
    cudaGetSymbolAddress((void**)&wqh, g_wq_h); cudaGetSymbolAddress((void**)&wql, g_wq_l);
    cudaGetSymbolAddress((void**)&wkh, g_wk_h); cudaGetSymbolAddress((void**)&wkl, g_wk_l);
    cudaGetSymbolAddress((void**)&wvh, g_wv_h); cudaGetSymbolAddress((void**)&wvl, g_wv_l);
    cudaGetSymbolAddress((void**)&woh, g_wo_h); cudaGetSymbolAddress((void**)&wol, g_wo_l);
    cudaGetSymbolAddress((void**)&ch, g_c_h);   cudaGetSymbolAddress((void**)&cl, g_c_l);
    cudaGetSymbolAddress((void**)&qh, g_qh);    cudaGetSymbolAddress((void**)&ql, g_ql);
    cudaGetSymbolAddress((void**)&kh, g_kh);    cudaGetSymbolAddress((void**)&kl, g_kl);
    cudaGetSymbolAddress((void**)&vh, g_vh);    cudaGetSymbolAddress((void**)&vl, g_vl);

    cudaFuncSetAttribute(gemm_hmma, cudaFuncAttributeMaxDynamicSharedMemorySize, GSM_BYTES);
    cudaFuncSetAttribute(attn_hmma, cudaFuncAttributeMaxDynamicSharedMemorySize, AT_SMEM);

    rope_table<<<(SS * 64 + 255) / 256, 256>>>();

    {
        int n;
        n = MTOK * HIDN / 4; cvt_split<<<(n + 255) / 256, 256>>>(hs, hsh, hsl, n);
        n = HIDN * HIDN / 4; cvt_split<<<(n + 255) / 256, 256>>>(Wq, wqh, wql, n);
        n = KVW * HIDN / 4;  cvt_split<<<(n + 255) / 256, 256>>>(Wk, wkh, wkl, n);
        n = KVW * HIDN / 4;  cvt_split<<<(n + 255) / 256, 256>>>(Wv, wvh, wvl, n);
        n = HIDN * HIDN / 4; cvt_split<<<(n + 255) / 256, 256>>>(Wo, woh, wol, n);
    }

    gemm_hmma<<<dim3(HIDN / 128, MTOK / 128), 256, GSM_BYTES>>>(hsh, hsl, wqh, wql, qp, MTOK, HIDN, HIDN);
    gemm_hmma<<<dim3(KVW / 128, MTOK / 128), 256, GSM_BYTES>>>(hsh, hsl, wkh, wkl, kp, MTOK, KVW, HIDN);
    gemm_hmma<<<dim3(KVW / 128, MTOK / 128), 256, GSM_BYTES>>>(hsh, hsl, wvh, wvl, vp, MTOK, KVW, HIDN);

    rope_apply<<<(MTOK * NH * 64 + 255) / 256, 256>>>(qp, NH);
    rope_apply<<<(MTOK * NKV * 64 + 255) / 256, 256>>>(kp, NKV);

    // convert rope'd Q (scale folded), K, V to bf16 hi/lo
    {
        int n;
        const float scale = 0.08838834764831845f;  // 1/sqrt(128)
        n = MTOK * HIDN / 4; cvt_split_s<<<(n + 255) / 256, 256>>>(qp, qh, ql, n, scale);
        n = MTOK * KVW / 4;  cvt_split<<<(n + 255) / 256, 256>>>(kp, kh, kl, n);
        n = MTOK * KVW / 4;  cvt_split<<<(n + 255) / 256, 256>>>(vp, vh, vl, n);
    }

    attn_hmma<<<dim3(SS / 64, NH, BB), 128, AT_SMEM>>>(qh, ql, kh, kl, vh, vl, cp);

    {
        int n = MTOK * HIDN / 4;
        cvt_split<<<(n + 255) / 256, 256>>>(cp, ch, cl, n);
    }
    gemm_hmma<<<dim3(HIDN / 128, MTOK / 128), 256, GSM_BYTES>>>(ch, cl, woh, wol, out, MTOK, HIDN, HIDN);
}